// round 17
// baseline (speedup 1.0000x reference)
#include <cuda_runtime.h>
#include <cuda_bf16.h>
#include <math.h>

// Problem constants
#define BATCH 2048
#define FEAT 256
#define TREES 256
#define DEPTH 6
#define NCOLS (TREES * DEPTH)   // 1536
#define LEAVES 64
#define NNZ_ST 40               // list stride/capacity (support ~23, +7 sigma)
#define T_TILE 16               // trees per block in K2

// Scratch (device globals: no allocation allowed)
__device__ __align__(16) float    g_w[NCOLS * NNZ_ST];   // weights, zero-padded to NNZ_ST
__device__ __align__(16) unsigned g_o[NCOLS * NNZ_ST];   // xs2 byte offsets = idx*264
__device__ __align__(16) float4   g_meta[NCOLS];         // {threshold, exp(-logtemp), nround, 0}

// ---------------------------------------------------------------------------
// Kernel 1: exact sparsemax via Michelot, ONE WARP PER COLUMN (no barriers).
// ---------------------------------------------------------------------------
__global__ __launch_bounds__(256) void k_sparsemax(
    const float* __restrict__ logits,
    const float* __restrict__ thresholds,
    const float* __restrict__ logtemp)
{
    const int col = blockIdx.x * 8 + (threadIdx.x >> 5);
    const int ln  = threadIdx.x & 31;

    float v[8];
    #pragma unroll
    for (int j = 0; j < 8; j++)
        v[j] = logits[(j * 32 + ln) * NCOLS + col];

    // ---- warp max ----
    float m = v[0];
    #pragma unroll
    for (int j = 1; j < 8; j++) m = fmaxf(m, v[j]);
    #pragma unroll
    for (int o = 16; o; o >>= 1) m = fmaxf(m, __shfl_xor_sync(0xffffffffu, m, o));
    #pragma unroll
    for (int j = 0; j < 8; j++) v[j] -= m;

    // ---- Michelot iterations (exact sparsemax tau) ----
    unsigned actm = 0xFFu;
    float tau = 0.0f;
    int prevcnt = -1;
    #pragma unroll 1
    for (int it = 0; it < 64; it++) {
        float s = 0.0f; int c = 0;
        #pragma unroll
        for (int j = 0; j < 8; j++) {
            if (actm & (1u << j)) { s += v[j]; c++; }
        }
        #pragma unroll
        for (int o = 16; o; o >>= 1) s += __shfl_xor_sync(0xffffffffu, s, o);
        c = __reduce_add_sync(0xffffffffu, c);
        tau = (s - 1.0f) / (float)c;
        if (c == prevcnt) break;      // support stable -> converged (exact)
        prevcnt = c;
        unsigned nm = 0u;
        #pragma unroll
        for (int j = 0; j < 8; j++) if (v[j] > tau) nm |= (1u << j);
        actm = nm;
    }

    // ---- weights + compaction (order irrelevant to the dot product) ----
    const unsigned ltmask = (1u << ln) - 1u;
    int base = 0;
    #pragma unroll
    for (int j = 0; j < 8; j++) {
        const float w = fmaxf(v[j] - tau, 0.0f);
        const bool nz = (w > 0.0f);
        const unsigned bal = __ballot_sync(0xffffffffu, nz);
        const int pos = base + __popc(bal & ltmask);
        if (nz && pos < NNZ_ST) {
            g_w[col * NNZ_ST + pos] = w;
            g_o[col * NNZ_ST + pos] = (unsigned)(j * 32 + ln) * 264u;
        }
        base += __popc(bal);
    }

    int tot = base < NNZ_ST ? base : NNZ_ST;
    for (int p = tot + ln; p < NNZ_ST; p += 32) {    // zero-pad to capacity
        g_w[col * NNZ_ST + p] = 0.0f;
        g_o[col * NNZ_ST + p] = 0u;
    }
    if (ln == 0) {
        const float th = thresholds[col];
        const float sc = expf(-logtemp[col]);
        const int nround = (tot + 7) & ~7;           // mult of 8 (K2 chunk)
        g_meta[col] = make_float4(th, sc, __int_as_float(nround), 0.0f);
    }
}

// ---------------------------------------------------------------------------
// Kernel 2: fused sparse contraction + tree evaluation, ALL-SMEM inner loop.
// Tile: 64 batch x 16 trees (256 threads, 8 warps; 2 trees/warp).
// 8-entry chunks per depth-pair (~60-slot pipeline stage covers 29-cyc LDS).
// Merged epilogue with 4-way split accumulators.
// smem = 103,936 B -> 2 blocks/SM (128-reg budget).
// ---------------------------------------------------------------------------
#define XS2_OFF   0
#define XS2_SZ    (FEAT * 33 * 8)              // 67584
#define WL_OFF    (XS2_OFF + XS2_SZ)
#define WL_SZ     (T_TILE * DEPTH * NNZ_ST * 4)   // 15360
#define OL_OFF    (WL_OFF + WL_SZ)
#define OL_SZ     (T_TILE * DEPTH * NNZ_ST * 4)   // 15360
#define RS2_OFF   (OL_OFF + OL_SZ)
#define RS2_SZ    (T_TILE * 32 * 8)            // 4096
#define MT_OFF    (RS2_OFF + RS2_SZ)
#define MT_SZ     (T_TILE * DEPTH * 16)        // 1536
#define SMEM_TOT  (MT_OFF + MT_SZ)             // 103936

__global__ __launch_bounds__(256, 2) void k_forest(
    const float* __restrict__ x,
    const float* __restrict__ response,
    float* __restrict__ out)
{
    extern __shared__ char smem[];
    float2*   xs2   = (float2*)(smem + XS2_OFF);   // [f][pair], pitch 33
    float*    swl   = (float*)(smem + WL_OFF);     // [96][40] weights
    unsigned* sol   = (unsigned*)(smem + OL_OFF);  // [96][40] offsets
    float2*   rs2   = (float2*)(smem + RS2_OFF);   // [tree][32] = {r[i], r[i+32]}
    float4*   smeta = (float4*)(smem + MT_OFF);    // [96]
    float2*   outs2 = (float2*)(smem + XS2_OFF);   // reused AFTER tree loop

    const int tid  = threadIdx.x;
    const int lane = tid & 31;
    const int warp = tid >> 5;
    const int b0 = blockIdx.x * 64;
    const int t0 = blockIdx.y * T_TILE;
    const int colb0 = t0 * DEPTH;                  // 96 contiguous columns

    // ---- stage lists + meta (coalesced, high MLP) ----
    {
        const float4* gw4 = (const float4*)(g_w + colb0 * NNZ_ST);
        const uint4*  go4 = (const uint4*)(g_o + colb0 * NNZ_ST);
        float4* sw4 = (float4*)swl;
        uint4*  so4 = (uint4*)sol;
        #pragma unroll
        for (int i = tid; i < (T_TILE * DEPTH * NNZ_ST) / 4; i += 256) {
            sw4[i] = __ldg(gw4 + i);
            so4[i] = __ldg(go4 + i);
        }
        if (tid < T_TILE * DEPTH) smeta[tid] = __ldg(&g_meta[colb0 + tid]);
    }

    // ---- stage x tile ----
    #pragma unroll 4
    for (int p = 0; p < 32; p++) {
        float lo = x[(b0 + 2 * p    ) * FEAT + tid];
        float hi = x[(b0 + 2 * p + 1) * FEAT + tid];
        xs2[tid * 33 + p] = make_float2(lo, hi);
    }
    // ---- stage response, packed (i, i+32) ----
    #pragma unroll
    for (int i = tid; i < T_TILE * 32; i += 256) {
        const int tr = i >> 5, lf = i & 31;
        const float* rr = response + (t0 + tr) * LEAVES;
        rs2[i] = make_float2(rr[lf], rr[lf + 32]);
    }
    __syncthreads();

    const char* xbl = (const char*)xs2 + lane * 8;   // lane-fixed byte base

    float2 ov[2];                                    // deferred outputs (2 trees)

    #pragma unroll 1
    for (int tq = 0; tq < 2; tq++) {
        const int tt = warp + tq * 8;
        const int clb = tt * DEPTH;                  // local column base (0..95)

        float svl[DEPTH], svh[DEPTH];

        // process depths in pairs (d, d+1)
        #pragma unroll
        for (int dp = 0; dp < DEPTH; dp += 2) {
            const float4 m0 = smeta[clb + dp];
            const float4 m1 = smeta[clb + dp + 1];
            const int n0 = __float_as_int(m0.z);
            const int n1 = __float_as_int(m1.z);
            const int n  = n0 > n1 ? n0 : n1;        // mult of 8, <= NNZ_ST

            const float*    __restrict__ w0 = swl + (clb + dp    ) * NNZ_ST;
            const float*    __restrict__ w1 = swl + (clb + dp + 1) * NNZ_ST;
            const unsigned* __restrict__ o0 = sol + (clb + dp    ) * NNZ_ST;
            const unsigned* __restrict__ o1 = sol + (clb + dp + 1) * NNZ_ST;

            float a0l = 0.f, a0h = 0.f, a1l = 0.f, a1h = 0.f;
            float b0l = 0.f, b0h = 0.f, b1l = 0.f, b1h = 0.f;

            // 8-entry chunks per depth, double-buffered (~60-slot stage)
            float4 wA0 = *(const float4*)(w0);
            float4 wB0 = *(const float4*)(w0 + 4);
            uint4  oA0 = *(const uint4*)(o0);
            uint4  oB0 = *(const uint4*)(o0 + 4);
            float4 wA1 = *(const float4*)(w1);
            float4 wB1 = *(const float4*)(w1 + 4);
            uint4  oA1 = *(const uint4*)(o1);
            uint4  oB1 = *(const uint4*)(o1 + 4);

            #define E(wv, off, AL, AH) {                                      \
                const float2 v2 = *(const float2*)(xbl + (off));              \
                AL = fmaf((wv), v2.x, AL); AH = fmaf((wv), v2.y, AH); }

            #define PROC16() {                                                \
                E(wA0.x, oA0.x, a0l, a0h); E(wA0.y, oA0.y, a1l, a1h);        \
                E(wA1.x, oA1.x, b0l, b0h); E(wA1.y, oA1.y, b1l, b1h);        \
                E(wA0.z, oA0.z, a0l, a0h); E(wA0.w, oA0.w, a1l, a1h);        \
                E(wA1.z, oA1.z, b0l, b0h); E(wA1.w, oA1.w, b1l, b1h);        \
                E(wB0.x, oB0.x, a0l, a0h); E(wB0.y, oB0.y, a1l, a1h);        \
                E(wB1.x, oB1.x, b0l, b0h); E(wB1.y, oB1.y, b1l, b1h);        \
                E(wB0.z, oB0.z, a0l, a0h); E(wB0.w, oB0.w, a1l, a1h);        \
                E(wB1.z, oB1.z, b0l, b0h); E(wB1.w, oB1.w, b1l, b1h); }

            #pragma unroll 1
            for (int j = 8; j < n; j += 8) {
                const float4 nwA0 = *(const float4*)(w0 + j);
                const float4 nwB0 = *(const float4*)(w0 + j + 4);
                const uint4  noA0 = *(const uint4*)(o0 + j);
                const uint4  noB0 = *(const uint4*)(o0 + j + 4);
                const float4 nwA1 = *(const float4*)(w1 + j);
                const float4 nwB1 = *(const float4*)(w1 + j + 4);
                const uint4  noA1 = *(const uint4*)(o1 + j);
                const uint4  noB1 = *(const uint4*)(o1 + j + 4);
                PROC16();
                wA0 = nwA0; wB0 = nwB0; oA0 = noA0; oB0 = noB0;
                wA1 = nwA1; wB1 = nwB1; oA1 = noA1; oB1 = noB1;
            }
            PROC16();
            #undef PROC16
            #undef E

            const float acc0l = a0l + a1l, acc0h = a0h + a1h;
            const float acc1l = b0l + b1l, acc1h = b0h + b1h;
            svl[dp]     = __saturatef(fmaf(0.5f, (acc0l - m0.x) * m0.y, 0.5f));
            svh[dp]     = __saturatef(fmaf(0.5f, (acc0h - m0.x) * m0.y, 0.5f));
            svl[dp + 1] = __saturatef(fmaf(0.5f, (acc1l - m1.x) * m1.y, 0.5f));
            svh[dp + 1] = __saturatef(fmaf(0.5f, (acc1h - m1.x) * m1.y, 0.5f));
        }

        // ---- merged epilogue: both product trees, shared r2 pass,
        //      4-way split accumulators per half ----
        float al[32], ah[32];
        al[0] = 1.0f; ah[0] = 1.0f;
        #pragma unroll
        for (int d = 0; d < 5; d++) {
            const float sdl = svl[d], cdl = 1.0f - svl[d];
            const float sdh = svh[d], cdh = 1.0f - svh[d];
            #pragma unroll
            for (int i = (1 << d) - 1; i >= 0; i--) {
                const float a = al[i], b = ah[i];
                al[i + (1 << d)] = a * cdl;  al[i] = a * sdl;
                ah[i + (1 << d)] = b * cdh;  ah[i] = b * sdh;
            }
        }
        const float2* __restrict__ r2 = rs2 + tt * 32;
        const float s5l = svl[5], c5l = 1.0f - svl[5];
        const float s5h = svh[5], c5h = 1.0f - svh[5];
        float ol0 = 0.f, ol1 = 0.f, ol2 = 0.f, ol3 = 0.f;
        float oh0 = 0.f, oh1 = 0.f, oh2 = 0.f, oh3 = 0.f;
        #pragma unroll
        for (int i = 0; i < 32; i += 4) {
            const float2 q0 = r2[i], q1 = r2[i+1], q2 = r2[i+2], q3 = r2[i+3];
            ol0 = fmaf(al[i  ], fmaf(s5l, q0.x, c5l * q0.y), ol0);
            ol1 = fmaf(al[i+1], fmaf(s5l, q1.x, c5l * q1.y), ol1);
            ol2 = fmaf(al[i+2], fmaf(s5l, q2.x, c5l * q2.y), ol2);
            ol3 = fmaf(al[i+3], fmaf(s5l, q3.x, c5l * q3.y), ol3);
            oh0 = fmaf(ah[i  ], fmaf(s5h, q0.x, c5h * q0.y), oh0);
            oh1 = fmaf(ah[i+1], fmaf(s5h, q1.x, c5h * q1.y), oh1);
            oh2 = fmaf(ah[i+2], fmaf(s5h, q2.x, c5h * q2.y), oh2);
            oh3 = fmaf(ah[i+3], fmaf(s5h, q3.x, c5h * q3.y), oh3);
        }
        ov[tq] = make_float2((ol0 + ol1) + (ol2 + ol3),
                             (oh0 + oh1) + (oh2 + oh3));
    }

    // xs2 no longer needed -> reuse as output staging (pitch 33)
    __syncthreads();
    #pragma unroll
    for (int tq = 0; tq < 2; tq++) {
        outs2[(warp + tq * 8) * 33 + lane] = ov[tq];
    }
    __syncthreads();

    // coalesced store of the 64x16 output tile
    const int tl  = tid & 15;            // tree
    const int grp = tid >> 4;            // pair group (0..15)
    #pragma unroll
    for (int q = 0; q < 2; q++) {
        const int p = grp * 2 + q;       // batch pair 0..31
        const float2 v = outs2[tl * 33 + p];
        out[(b0 + 2 * p    ) * TREES + t0 + tl] = v.x;
        out[(b0 + 2 * p + 1) * TREES + t0 + tl] = v.y;
    }
}

// ---------------------------------------------------------------------------
extern "C" void kernel_launch(void* const* d_in, const int* in_sizes, int n_in,
                              void* d_out, int out_size)
{
    const float* x    = (const float*)d_in[0];   // [2048, 256]
    const float* resp = (const float*)d_in[1];   // [256, 1, 64]
    const float* fsl  = (const float*)d_in[2];   // [256, 256, 6]
    const float* th   = (const float*)d_in[3];   // [256, 6]
    const float* lt   = (const float*)d_in[4];   // [256, 6]
    float* out        = (float*)d_out;           // [2048, 256]

    cudaFuncSetAttribute(k_forest, cudaFuncAttributeMaxDynamicSharedMemorySize, SMEM_TOT);

    k_sparsemax<<<NCOLS / 8, 256>>>(fsl, th, lt);
    dim3 g2(BATCH / 64, TREES / T_TILE);
    k_forest<<<g2, 256, SMEM_TOT>>>(x, resp, out);
}